// round 4
// baseline (speedup 1.0000x reference)
#include <cuda_runtime.h>
#include <cuda_bf16.h>
#include <stdint.h>

// ============================================================================
// Llama4TextExperts grouped GEMM + SwiGLU, fp32 in/out.
// Portable tensor path: mma.sync.m16n8k16 bf16 (sm_103 non-'a' safe).
// Accuracy: bf16x3 split  a*b ~= ah*bh + ah*bl + al*bh, fp32 accumulate.
//   GEMM1: X(8,1024,2048) @ Wgu(8,2048,8192) -> g_gu (fp32 scratch)
//   GEMM2: SwiGLU(g_gu) (8,1024,4096) @ Wd(8,4096,2048) -> out(8192,2048)
// ============================================================================

#define GU_W 8192
#define FDIM 4096

static __device__ float g_gu[(size_t)8 * 1024 * GU_W];   // 256 MB scratch

// Stage layout (64 KB): Ah[128][64]bf16 @0, Al @16K, Bh[64][128]bf16 @32K, Bl @48K
#define STAGE_BYTES 65536
#define SMEM_BYTES  (1024 + 2 * STAGE_BYTES)

// ---------------- helpers ----------------
__device__ __forceinline__ uint32_t s2u(const void* p) {
    uint32_t a;
    asm("{ .reg .u64 t; cvta.to.shared.u64 t, %1; cvt.u32.u64 %0, t; }" : "=r"(a) : "l"(p));
    return a;
}
// A tiles: 128-byte rows. XOR row bits[0:3) (offset bits 7-9) into byte bits 4-6.
__device__ __forceinline__ uint32_t swzA(uint32_t o) { return o ^ ((o >> 3) & 0x70); }
// B tiles: 256-byte rows. XOR row bits (offset bits 8-10) into byte bits 4-6.
__device__ __forceinline__ uint32_t swzB(uint32_t o) { return o ^ ((o >> 4) & 0x70); }

__device__ __forceinline__ uint32_t pk(float a, float b) {
    __nv_bfloat162 h = __floats2bfloat162_rn(a, b);   // .x=a in low 16 bits
    return *reinterpret_cast<uint32_t*>(&h);
}

__device__ __forceinline__ void ldsm4(uint32_t* r, uint32_t addr) {
    asm volatile("ldmatrix.sync.aligned.m8n8.x4.shared.b16 {%0,%1,%2,%3}, [%4];"
                 : "=r"(r[0]), "=r"(r[1]), "=r"(r[2]), "=r"(r[3]) : "r"(addr));
}
__device__ __forceinline__ void ldsm4t(uint32_t* r, uint32_t addr) {
    asm volatile("ldmatrix.sync.aligned.m8n8.x4.trans.shared.b16 {%0,%1,%2,%3}, [%4];"
                 : "=r"(r[0]), "=r"(r[1]), "=r"(r[2]), "=r"(r[3]) : "r"(addr));
}
__device__ __forceinline__ void mma16816(float* c, const uint32_t* a, const uint32_t* b) {
    asm volatile(
        "mma.sync.aligned.m16n8k16.row.col.f32.bf16.bf16.f32 "
        "{%0,%1,%2,%3}, {%4,%5,%6,%7}, {%8,%9}, {%0,%1,%2,%3};"
        : "+f"(c[0]), "+f"(c[1]), "+f"(c[2]), "+f"(c[3])
        : "r"(a[0]), "r"(a[1]), "r"(a[2]), "r"(a[3]), "r"(b[0]), "r"(b[1]));
}

// ============================================================================
//   KDIM : reduction dim (2048 / 4096)
//   NW   : B & C row width (8192 / 2048)
//   NTILE: 128-col N tiles per expert (64 / 16)
//   SWIGLU: A = up * silu(gate) streamed from g_gu (GEMM2)
// Block: 512 threads = 16 warps in a 4(m) x 4(n) grid, 32x32 warp tiles.
// ============================================================================
template <int KDIM, int NW, int NTILE, bool SWIGLU>
__global__ __launch_bounds__(512, 1) void gemm_ker(const float* __restrict__ Ain,
                                                   const float* __restrict__ Bin,
                                                   float* __restrict__ Cout) {
    extern __shared__ char smem[];
    constexpr int NC = KDIM / 64;

    const int tid  = threadIdx.x;
    const int wid  = tid >> 5;
    const int lane = tid & 31;
    const int wm   = wid & 3;          // warp m index (rows wm*32)
    const int wn   = wid >> 2;         // warp n index (cols wn*32)

    // ---- tile decode: 64-CTA (8m x 8n) supertiles for L2 reuse ----
    const int per_e = 8 * NTILE;
    const int e   = blockIdx.x / per_e;
    const int r   = blockIdx.x % per_e;
    const int sup = r >> 6;
    const int r2  = r & 63;
    const int mt  = r2 & 7;
    const int nt  = sup * 8 + (r2 >> 3);

    const float* Asrc  = SWIGLU ? (const float*)g_gu : Ain;
    float*       Cbase = SWIGLU ? Cout : (float*)g_gu;
    const int AW = SWIGLU ? GU_W : KDIM;

    const float* Ae = Asrc + (size_t)(e * 1024 + mt * 128) * AW;
    const float* Be = Bin + (size_t)e * KDIM * NW + nt * 128;
    float*       Ce = Cbase + (size_t)(e * 1024 + mt * 128) * NW + nt * 128;

    const uint32_t smbase  = s2u(smem);
    const uint32_t tiles_u = (smbase + 1023) & ~1023u;
    char* tiles = smem + (tiles_u - smbase);

    // ---- loader thread mapping (per chunk of Kc=64) ----
    const int a_c4  = tid & 15;        // float4 col within 64-k row
    const int a_r0  = tid >> 4;        // base row 0..31 (stride 32)
    const int b_n4  = tid & 31;        // float4 col within 128-n row
    const int b_k0  = tid >> 5;        // base k 0..15 (stride 16)

    // ---- ldmatrix lane addressing (constants per lane) ----
    const int lane15 = lane & 15;
    const int seg    = (lane >> 4) * 16;       // 16B segment select
    const uint32_t lxor = (uint32_t)((lane & 7) << 4);
    uint32_t a_row[2], b_colx[2];
    #pragma unroll
    for (int st = 0; st < 2; st++)
        a_row[st] = (uint32_t)((wm * 32 + st * 16 + lane15) * 128);
    #pragma unroll
    for (int ng = 0; ng < 2; ng++)
        b_colx[ng] = (uint32_t)(((wn * 32 + ng * 16) * 2 + seg)) ^ lxor;
    const uint32_t b_rowb = (uint32_t)(lane15 * 256);

    float acc[2][4][4];
    #pragma unroll
    for (int st = 0; st < 2; st++)
        #pragma unroll
        for (int j = 0; j < 4; j++)
            #pragma unroll
            for (int i = 0; i < 4; i++) acc[st][j][i] = 0.0f;

    for (int c = 0; c < NC; c++) {
        char* stg = tiles + (c & 1) * STAGE_BYTES;
        const int kbase = c * 64;

        // ---------------- load + convert + split + store ----------------
        // A tile: 128 rows x 64 k (fp32 -> bf16 hi/lo), rows are 128B
        #pragma unroll
        for (int p = 0; p < 4; p++) {
            const int row = a_r0 + p * 32;
            const float* sa = Ae + (size_t)row * AW + kbase + a_c4 * 4;
            float v[4];
            *reinterpret_cast<float4*>(v) = *reinterpret_cast<const float4*>(sa);
            if (SWIGLU) {
                float u[4];
                *reinterpret_cast<float4*>(u) = *reinterpret_cast<const float4*>(sa + FDIM);
                #pragma unroll
                for (int j = 0; j < 4; j++)
                    v[j] = u[j] * (v[j] / (1.0f + __expf(-v[j])));
            }
            float h[4], l[4];
            #pragma unroll
            for (int j = 0; j < 4; j++) {
                h[j] = __bfloat162float(__float2bfloat16(v[j]));
                l[j] = v[j] - h[j];
            }
            const uint32_t off = swzA((uint32_t)(row * 128 + a_c4 * 8));
            *reinterpret_cast<uint2*>(stg + off)         = make_uint2(pk(h[0], h[1]), pk(h[2], h[3]));
            *reinterpret_cast<uint2*>(stg + 16384 + off) = make_uint2(pk(l[0], l[1]), pk(l[2], l[3]));
        }
        // B tile: 64 k-rows x 128 n (natural [k][n]), rows are 256B
        #pragma unroll
        for (int p = 0; p < 4; p++) {
            const int k = b_k0 + p * 16;
            const float* sb = Be + (size_t)(kbase + k) * NW + b_n4 * 4;
            float v[4];
            *reinterpret_cast<float4*>(v) = *reinterpret_cast<const float4*>(sb);
            float h[4], l[4];
            #pragma unroll
            for (int j = 0; j < 4; j++) {
                h[j] = __bfloat162float(__float2bfloat16(v[j]));
                l[j] = v[j] - h[j];
            }
            const uint32_t off = swzB((uint32_t)(k * 256 + b_n4 * 8));
            *reinterpret_cast<uint2*>(stg + 32768 + off) = make_uint2(pk(h[0], h[1]), pk(h[2], h[3]));
            *reinterpret_cast<uint2*>(stg + 49152 + off) = make_uint2(pk(l[0], l[1]), pk(l[2], l[3]));
        }

        __syncthreads();

        // ---------------- MMA over the stage (4 x k16 steps) ----------------
        const uint32_t AhU = tiles_u + (c & 1) * STAGE_BYTES;
        const uint32_t AlU = AhU + 16384;
        const uint32_t BhU = AhU + 32768;
        const uint32_t BlU = AhU + 49152;

        #pragma unroll
        for (int ks = 0; ks < 4; ks++) {
            const uint32_t acol = (uint32_t)(ks * 32 + seg) ^ lxor;
            const uint32_t brow = b_rowb + (uint32_t)(ks * 4096);
            uint32_t ah[2][4], al[2][4], bh[2][4], bl[2][4];
            #pragma unroll
            for (int st = 0; st < 2; st++) {
                ldsm4(ah[st], AhU + a_row[st] + acol);
                ldsm4(al[st], AlU + a_row[st] + acol);
            }
            #pragma unroll
            for (int ng = 0; ng < 2; ng++) {
                ldsm4t(bh[ng], BhU + brow + b_colx[ng]);
                ldsm4t(bl[ng], BlU + brow + b_colx[ng]);
            }
            #pragma unroll
            for (int st = 0; st < 2; st++)
                #pragma unroll
                for (int ng = 0; ng < 2; ng++)
                    #pragma unroll
                    for (int hf = 0; hf < 2; hf++) {
                        const int j = ng * 2 + hf;
                        mma16816(acc[st][j], ah[st], &bh[ng][2 * hf]);
                        mma16816(acc[st][j], ah[st], &bl[ng][2 * hf]);
                        mma16816(acc[st][j], al[st], &bh[ng][2 * hf]);
                    }
        }
        // no trailing sync: next iteration writes the other buffer; the
        // next __syncthreads() fences reuse of this one.
    }

    // ---------------- epilogue: fp32 stores straight from accumulators ----
    #pragma unroll
    for (int st = 0; st < 2; st++)
        #pragma unroll
        for (int j = 0; j < 4; j++) {
            const int r0 = wm * 32 + st * 16 + (lane >> 2);
            const int cc = wn * 32 + j * 8 + (lane & 3) * 2;
            float2 v0; v0.x = acc[st][j][0]; v0.y = acc[st][j][1];
            float2 v1; v1.x = acc[st][j][2]; v1.y = acc[st][j][3];
            *reinterpret_cast<float2*>(Ce + (size_t)r0 * NW + cc) = v0;
            *reinterpret_cast<float2*>(Ce + (size_t)(r0 + 8) * NW + cc) = v1;
        }
}

// ============================================================================
extern "C" void kernel_launch(void* const* d_in, const int* in_sizes, int n_in,
                              void* d_out, int out_size) {
    const float* X   = (const float*)d_in[0];   // (8192, 2048)
    const float* Wgu = (const float*)d_in[1];   // (8, 2048, 8192)
    const float* Wd  = (const float*)d_in[2];   // (8, 4096, 2048)
    float* out = (float*)d_out;                 // (8192, 2048)

    cudaFuncSetAttribute(gemm_ker<2048, 8192, 64, false>,
                         cudaFuncAttributeMaxDynamicSharedMemorySize, SMEM_BYTES);
    cudaFuncSetAttribute(gemm_ker<4096, 2048, 16, true>,
                         cudaFuncAttributeMaxDynamicSharedMemorySize, SMEM_BYTES);

    // GEMM1: 8 experts * 8 mtiles * 64 ntiles = 4096 CTAs
    gemm_ker<2048, 8192, 64, false><<<4096, 512, SMEM_BYTES>>>(X, Wgu, nullptr);
    // GEMM2 (SwiGLU fused in A-loader): 8 * 8 * 16 = 1024 CTAs
    gemm_ker<4096, 2048, 16, true><<<1024, 512, SMEM_BYTES>>>(nullptr, Wd, out);
}

// round 5
// speedup vs baseline: 1.5711x; 1.5711x over previous
#include <cuda_runtime.h>
#include <cuda_bf16.h>
#include <stdint.h>

// ============================================================================
// Llama4TextExperts grouped GEMM + SwiGLU, fp32 in/out.
// mma.sync.m16n8k16 bf16 (sm_103-safe), bf16x3 split (ah*bh + ah*bl + al*bh).
// Warp-specialized: 16 consumer (MMA) warps + 4 producer warps, 3-stage ring.
//   GEMM1: X(8,1024,2048) @ Wgu(8,2048,8192) -> SwiGLU -> g_scr packed(hi,lo)
//   GEMM2: g_scr(8,1024,4096) @ Wd(8,4096,2048) -> out(8192,2048) fp32
// ============================================================================

#define STAGE_BYTES 65536
#define NSTAGE 3
#define SMEM_BYTES (1024 + NSTAGE * STAGE_BYTES)

// packed intermediate: u32 = (bf16 hi << 16) | bf16 lo
static __device__ uint32_t g_scr[(size_t)8 * 1024 * 4096];   // 128 MB

// ---------------- helpers ----------------
__device__ __forceinline__ uint32_t s2u(const void* p) {
    uint32_t a;
    asm("{ .reg .u64 t; cvta.to.shared.u64 t, %1; cvt.u32.u64 %0, t; }" : "=r"(a) : "l"(p));
    return a;
}
__device__ __forceinline__ uint32_t swzA(uint32_t o) { return o ^ ((o >> 3) & 0x70); }  // 128B rows
__device__ __forceinline__ uint32_t swzB(uint32_t o) { return o ^ ((o >> 4) & 0x70); }  // 256B rows

__device__ __forceinline__ uint32_t pk(float a, float b) {
    __nv_bfloat162 h = __floats2bfloat162_rn(a, b);   // .x=a in low 16 bits
    return *reinterpret_cast<uint32_t*>(&h);
}
// split two fp32 into bf16 hi-pair (truncation, exact) and lo-pair (residual)
__device__ __forceinline__ void split2(float f0, float f1, uint32_t& hi, uint32_t& lo) {
    const uint32_t u0 = __float_as_uint(f0), u1 = __float_as_uint(f1);
    asm("prmt.b32 %0, %1, %2, 0x7632;" : "=r"(hi) : "r"(u0), "r"(u1));
    const float h0 = __uint_as_float(u0 & 0xFFFF0000u);
    const float h1 = __uint_as_float(u1 & 0xFFFF0000u);
    lo = pk(f0 - h0, f1 - h1);
}
__device__ __forceinline__ uint32_t pack_hl(float f) {
    __nv_bfloat16 hb = __float2bfloat16(f);
    float hf = __bfloat162float(hb);
    __nv_bfloat16 lb = __float2bfloat16(f - hf);
    return ((uint32_t)__bfloat16_as_ushort(hb) << 16) | (uint32_t)__bfloat16_as_ushort(lb);
}

__device__ __forceinline__ void ldsm4(uint32_t* r, uint32_t addr) {
    asm volatile("ldmatrix.sync.aligned.m8n8.x4.shared.b16 {%0,%1,%2,%3}, [%4];"
                 : "=r"(r[0]), "=r"(r[1]), "=r"(r[2]), "=r"(r[3]) : "r"(addr));
}
__device__ __forceinline__ void ldsm4t(uint32_t* r, uint32_t addr) {
    asm volatile("ldmatrix.sync.aligned.m8n8.x4.trans.shared.b16 {%0,%1,%2,%3}, [%4];"
                 : "=r"(r[0]), "=r"(r[1]), "=r"(r[2]), "=r"(r[3]) : "r"(addr));
}
__device__ __forceinline__ void mma16816(float* c, const uint32_t* a, const uint32_t* b) {
    asm volatile(
        "mma.sync.aligned.m16n8k16.row.col.f32.bf16.bf16.f32 "
        "{%0,%1,%2,%3}, {%4,%5,%6,%7}, {%8,%9}, {%0,%1,%2,%3};"
        : "+f"(c[0]), "+f"(c[1]), "+f"(c[2]), "+f"(c[3])
        : "r"(a[0]), "r"(a[1]), "r"(a[2]), "r"(a[3]), "r"(b[0]), "r"(b[1]));
}

#define MBAR_INIT(addr, cnt) \
    asm volatile("mbarrier.init.shared.b64 [%0], %1;" :: "r"(addr), "r"((uint32_t)(cnt)) : "memory")
#define MBAR_ARRIVE(addr) \
    asm volatile("mbarrier.arrive.shared.b64 _, [%0];" :: "r"(addr) : "memory")
#define MBAR_WAIT(mbar_addr, phase_parity) do {                                            \
    uint32_t _mbar = (uint32_t)(mbar_addr);                                                \
    uint32_t _par  = (uint32_t)(phase_parity);                                             \
    uint32_t _done;                                                                        \
    asm volatile(                                                                          \
        "{\n\t.reg .pred p;\n\t"                                                           \
        "mbarrier.try_wait.parity.acquire.cta.shared::cta.b64 p, [%1], %2;\n\t"            \
        "selp.b32 %0, 1, 0, p;\n\t}"                                                       \
        : "=r"(_done) : "r"(_mbar), "r"(_par) : "memory");                                 \
    if (!_done) {                                                                          \
        asm volatile(                                                                      \
            "{\n\t.reg .pred P1;\n\t"                                                      \
            "WL_%=:\n\t"                                                                   \
            "mbarrier.try_wait.parity.acquire.cta.shared::cta.b64 P1, [%0], %1, 0x989680;\n\t" \
            "@P1 bra.uni WD_%=;\n\t"                                                       \
            "bra.uni WL_%=;\n\t"                                                           \
            "WD_%=:\n\t}"                                                                  \
            :: "r"(_mbar), "r"(_par) : "memory");                                          \
    }                                                                                      \
} while (0)

// ============================================================================
//   KDIM : reduction dim (2048 / 4096),  NTILE: n-tiles per expert (64 / 16)
//   MODE2=false: GEMM1 (A = X fp32 w2048; B = Wgu w8192, paired gate/up cols;
//                       epilogue SwiGLU -> packed g_scr, tile 128x64)
//   MODE2=true : GEMM2 (A = g_scr packed w4096; B = Wd w2048; C fp32 w2048)
// Block: 640 threads = 16 consumer warps (4x4, 32x32 tiles) + 4 producer warps.
// ============================================================================
template <int KDIM, int NTILE, bool MODE2>
__global__ __launch_bounds__(640, 1) void gemm_ker(const float* __restrict__ A_,
                                                   const float* __restrict__ B_,
                                                   float* __restrict__ C_) {
    extern __shared__ char smem[];
    constexpr int NC  = KDIM / 64;
    constexpr int NWB = MODE2 ? 2048 : 8192;   // B row width

    const int tid  = threadIdx.x;
    const int wid  = tid >> 5;
    const int lane = tid & 31;

    // ---- tile decode: 64-CTA (8m x 8n) supertiles ----
    const int per_e = 8 * NTILE;
    const int e   = blockIdx.x / per_e;
    const int r   = blockIdx.x % per_e;
    const int sup = r >> 6;
    const int r2  = r & 63;
    const int mt  = r2 & 7;
    const int nt  = sup * 8 + (r2 >> 3);

    const uint32_t smbase  = s2u(smem);
    const uint32_t tiles_u = (smbase + 1023) & ~1023u;
    char* tiles = smem + (tiles_u - smbase);
    const uint32_t full0  = smbase;        // full[s]  @ +8s, count=128
    const uint32_t empty0 = smbase + 24;   // empty[s] @ +8s, count=16

    if (tid == 0) {
        #pragma unroll
        for (int s = 0; s < NSTAGE; s++) {
            MBAR_INIT(full0 + 8 * s, 128);
            MBAR_INIT(empty0 + 8 * s, 16);
        }
    }
    __syncthreads();

    if (tid >= 512) {
        // ===================== PRODUCERS (warps 16..19) =====================
        const int pt   = tid - 512;          // 0..127
        const int a_c4 = pt & 15;            // float4/uint4 col in 64-k row
        const int a_r0 = pt >> 4;            // 0..7
        const int b_n4 = pt & 31;            // vec4 col in 128-n row
        const int b_k0 = pt >> 5;            // 0..3

        const float*    Apf = nullptr;
        const uint32_t* Apu = nullptr;
        if (MODE2) Apu = g_scr + (size_t)(e * 1024 + mt * 128) * 4096 + a_c4 * 4;
        else       Apf = A_ + (size_t)(e * 1024 + mt * 128) * 2048 + a_c4 * 4;

        size_t bcol;
        if (MODE2) bcol = (size_t)nt * 128 + b_n4 * 4;
        else       bcol = (b_n4 < 16) ? ((size_t)nt * 64 + b_n4 * 4)
                                      : ((size_t)4096 + nt * 64 + (b_n4 - 16) * 4);
        const float* Bp = B_ + (size_t)e * KDIM * NWB + bcol;

        int s = 0, u = 0;
        for (int c = 0; c < NC; c++) {
            MBAR_WAIT(empty0 + 8 * s, u ^ 1);   // u=0: parity 1 passes immediately
            char* stg = tiles + s * STAGE_BYTES;
            const int kb = c * 64;

            // ---- A tile: 128 rows x 64 k ----
            #pragma unroll
            for (int p = 0; p < 16; p++) {
                const int row = a_r0 + p * 8;
                const uint32_t off = swzA((uint32_t)(row * 128 + a_c4 * 8));
                if (MODE2) {
                    uint4 v = *reinterpret_cast<const uint4*>(Apu + (size_t)row * 4096 + kb);
                    uint32_t h0, h1, l0, l1;
                    asm("prmt.b32 %0, %1, %2, 0x7632;" : "=r"(h0) : "r"(v.x), "r"(v.y));
                    asm("prmt.b32 %0, %1, %2, 0x5410;" : "=r"(l0) : "r"(v.x), "r"(v.y));
                    asm("prmt.b32 %0, %1, %2, 0x7632;" : "=r"(h1) : "r"(v.z), "r"(v.w));
                    asm("prmt.b32 %0, %1, %2, 0x5410;" : "=r"(l1) : "r"(v.z), "r"(v.w));
                    *reinterpret_cast<uint2*>(stg + off)         = make_uint2(h0, h1);
                    *reinterpret_cast<uint2*>(stg + 16384 + off) = make_uint2(l0, l1);
                } else {
                    float4 v = *reinterpret_cast<const float4*>(Apf + (size_t)row * 2048 + kb);
                    uint32_t h0, l0, h1, l1;
                    split2(v.x, v.y, h0, l0);
                    split2(v.z, v.w, h1, l1);
                    *reinterpret_cast<uint2*>(stg + off)         = make_uint2(h0, h1);
                    *reinterpret_cast<uint2*>(stg + 16384 + off) = make_uint2(l0, l1);
                }
            }
            // ---- B tile: 64 k-rows x 128 n ----
            #pragma unroll
            for (int p = 0; p < 16; p++) {
                const int k = b_k0 + p * 4;
                float4 v = *reinterpret_cast<const float4*>(Bp + (size_t)(kb + k) * NWB);
                uint32_t h0, l0, h1, l1;
                split2(v.x, v.y, h0, l0);
                split2(v.z, v.w, h1, l1);
                const uint32_t off = swzB((uint32_t)(k * 256 + b_n4 * 8));
                *reinterpret_cast<uint2*>(stg + 32768 + off) = make_uint2(h0, h1);
                *reinterpret_cast<uint2*>(stg + 49152 + off) = make_uint2(l0, l1);
            }
            MBAR_ARRIVE(full0 + 8 * s);
            if (++s == NSTAGE) { s = 0; u ^= 1; }
        }
        return;
    }

    // ======================= CONSUMERS (warps 0..15) =======================
    const int wm = wid & 3;
    const int wn = wid >> 2;

    const int lane15 = lane & 15;
    const int seg    = (lane >> 4) * 16;
    const uint32_t lxor = (uint32_t)((lane & 7) << 4);
    uint32_t a_row[2], b_colx[2];
    #pragma unroll
    for (int st = 0; st < 2; st++)
        a_row[st] = (uint32_t)((wm * 32 + st * 16 + lane15) * 128);
    #pragma unroll
    for (int ng = 0; ng < 2; ng++)
        b_colx[ng] = (uint32_t)(((wn * 32 + ng * 16) * 2 + seg)) ^ lxor;
    const uint32_t b_rowb = (uint32_t)(lane15 * 256);

    float acc[2][4][4];
    #pragma unroll
    for (int st = 0; st < 2; st++)
        #pragma unroll
        for (int j = 0; j < 4; j++)
            #pragma unroll
            for (int i = 0; i < 4; i++) acc[st][j][i] = 0.0f;

    int s = 0, u = 0;
    for (int c = 0; c < NC; c++) {
        MBAR_WAIT(full0 + 8 * s, u);
        const uint32_t AhU = tiles_u + s * STAGE_BYTES;
        const uint32_t AlU = AhU + 16384;
        const uint32_t BhU = AhU + 32768;
        const uint32_t BlU = AhU + 49152;

        #pragma unroll
        for (int ks = 0; ks < 4; ks++) {
            const uint32_t acol = (uint32_t)(ks * 32 + seg) ^ lxor;
            const uint32_t brow = b_rowb + (uint32_t)(ks * 4096);
            uint32_t ah[2][4], al[2][4], bh[2][4], bl[2][4];
            #pragma unroll
            for (int st = 0; st < 2; st++) {
                ldsm4(ah[st], AhU + a_row[st] + acol);
                ldsm4(al[st], AlU + a_row[st] + acol);
            }
            #pragma unroll
            for (int ng = 0; ng < 2; ng++) {
                ldsm4t(bh[ng], BhU + brow + b_colx[ng]);
                ldsm4t(bl[ng], BlU + brow + b_colx[ng]);
            }
            #pragma unroll
            for (int st = 0; st < 2; st++)
                #pragma unroll
                for (int ng = 0; ng < 2; ng++)
                    #pragma unroll
                    for (int hf = 0; hf < 2; hf++) {
                        const int j = ng * 2 + hf;
                        mma16816(acc[st][j], ah[st], &bh[ng][2 * hf]);
                        mma16816(acc[st][j], ah[st], &bl[ng][2 * hf]);
                        mma16816(acc[st][j], al[st], &bh[ng][2 * hf]);
                    }
        }
        // all LDSM of this stage complete (HMMAs consumed the frags)
        if (lane == 0) MBAR_ARRIVE(empty0 + 8 * s);
        if (++s == NSTAGE) { s = 0; u ^= 1; }
    }

    // --------------------------- epilogue ---------------------------
    if (MODE2) {
        // plain fp32 store to out (width 2048)
        float* Ce = C_ + (size_t)(e * 1024 + mt * 128) * 2048 + nt * 128;
        #pragma unroll
        for (int st = 0; st < 2; st++)
            #pragma unroll
            for (int j = 0; j < 4; j++) {
                const int r0 = wm * 32 + st * 16 + (lane >> 2);
                const int cc = wn * 32 + j * 8 + (lane & 3) * 2;
                float2 v0; v0.x = acc[st][j][0]; v0.y = acc[st][j][1];
                float2 v1; v1.x = acc[st][j][2]; v1.y = acc[st][j][3];
                *reinterpret_cast<float2*>(Ce + (size_t)r0 * 2048 + cc) = v0;
                *reinterpret_cast<float2*>(Ce + (size_t)(r0 + 8) * 2048 + cc) = v1;
            }
    } else {
        // SwiGLU: cols 0-63 = gate, 64-127 = up. Exchange gate via smem,
        // write inter = up * silu(gate) as packed (hi,lo) u32 to g_scr.
        constexpr int SGP = 68;   // gate pitch (floats), avoids bank conflicts
        float* sg = reinterpret_cast<float*>(tiles);
        asm volatile("bar.sync 1, 512;" ::: "memory");   // all consumers past MMA
        if (wn < 2) {
            #pragma unroll
            for (int st = 0; st < 2; st++)
                #pragma unroll
                for (int j = 0; j < 4; j++) {
                    const int r0 = wm * 32 + st * 16 + (lane >> 2);
                    const int cc = wn * 32 + j * 8 + (lane & 3) * 2;
                    float2 v0; v0.x = acc[st][j][0]; v0.y = acc[st][j][1];
                    float2 v1; v1.x = acc[st][j][2]; v1.y = acc[st][j][3];
                    *reinterpret_cast<float2*>(sg + (size_t)r0 * SGP + cc) = v0;
                    *reinterpret_cast<float2*>(sg + (size_t)(r0 + 8) * SGP + cc) = v1;
                }
        }
        asm volatile("bar.sync 1, 512;" ::: "memory");
        if (wn >= 2) {
            uint32_t* scrb = g_scr + (size_t)(e * 1024 + mt * 128) * 4096 + nt * 64;
            #pragma unroll
            for (int st = 0; st < 2; st++)
                #pragma unroll
                for (int j = 0; j < 4; j++) {
                    const int r0   = wm * 32 + st * 16 + (lane >> 2);
                    const int gcol = (wn - 2) * 32 + j * 8 + (lane & 3) * 2;
                    float2 g0 = *reinterpret_cast<float2*>(sg + (size_t)r0 * SGP + gcol);
                    float2 g1 = *reinterpret_cast<float2*>(sg + (size_t)(r0 + 8) * SGP + gcol);
                    float i0 = acc[st][j][0] * __fdividef(g0.x, 1.0f + __expf(-g0.x));
                    float i1 = acc[st][j][1] * __fdividef(g0.y, 1.0f + __expf(-g0.y));
                    float i2 = acc[st][j][2] * __fdividef(g1.x, 1.0f + __expf(-g1.x));
                    float i3 = acc[st][j][3] * __fdividef(g1.y, 1.0f + __expf(-g1.y));
                    *reinterpret_cast<uint2*>(scrb + (size_t)r0 * 4096 + gcol) =
                        make_uint2(pack_hl(i0), pack_hl(i1));
                    *reinterpret_cast<uint2*>(scrb + (size_t)(r0 + 8) * 4096 + gcol) =
                        make_uint2(pack_hl(i2), pack_hl(i3));
                }
        }
    }
}

// ============================================================================
extern "C" void kernel_launch(void* const* d_in, const int* in_sizes, int n_in,
                              void* d_out, int out_size) {
    const float* X   = (const float*)d_in[0];   // (8192, 2048)
    const float* Wgu = (const float*)d_in[1];   // (8, 2048, 8192)
    const float* Wd  = (const float*)d_in[2];   // (8, 4096, 2048)
    float* out = (float*)d_out;                 // (8192, 2048)

    cudaFuncSetAttribute(gemm_ker<2048, 64, false>,
                         cudaFuncAttributeMaxDynamicSharedMemorySize, SMEM_BYTES);
    cudaFuncSetAttribute(gemm_ker<4096, 16, true>,
                         cudaFuncAttributeMaxDynamicSharedMemorySize, SMEM_BYTES);

    // GEMM1 + SwiGLU: 8 experts * 8 mtiles * 64 gate/up-paired ntiles
    gemm_ker<2048, 64, false><<<4096, 640, SMEM_BYTES>>>(X, Wgu, nullptr);
    // GEMM2: 8 * 8 * 16
    gemm_ker<4096, 16, true><<<1024, 640, SMEM_BYTES>>>(nullptr, Wd, out);
}

// round 6
// speedup vs baseline: 1.8195x; 1.1581x over previous
#include <cuda_runtime.h>
#include <cuda_bf16.h>
#include <stdint.h>

// ============================================================================
// Llama4TextExperts grouped GEMM + SwiGLU, fp32 in/out.
// mma.sync.m16n8k16 bf16 (sm_103-safe), bf16x3 split (ah*bh + ah*bl + al*bh).
// Warp-specialized: 8 consumer (MMA) warps @ 64x32 + 4 producer warps, 3-stage.
//   GEMM1: X(8,1024,2048) @ Wgu(8,2048,8192) -> SwiGLU -> g_scr packed(hi,lo)
//   GEMM2: g_scr(8,1024,4096) @ Wd(8,4096,2048) -> out(8192,2048) fp32
// ============================================================================

#define STAGE_BYTES 65536
#define NSTAGE 3
#define SMEM_BYTES (1024 + NSTAGE * STAGE_BYTES)

// packed intermediate: u32 = (bf16 hi << 16) | bf16 lo
static __device__ uint32_t g_scr[(size_t)8 * 1024 * 4096];   // 128 MB

// ---------------- helpers ----------------
__device__ __forceinline__ uint32_t s2u(const void* p) {
    uint32_t a;
    asm("{ .reg .u64 t; cvta.to.shared.u64 t, %1; cvt.u32.u64 %0, t; }" : "=r"(a) : "l"(p));
    return a;
}
__device__ __forceinline__ uint32_t swzA(uint32_t o) { return o ^ ((o >> 3) & 0x70); }  // 128B rows
__device__ __forceinline__ uint32_t swzB(uint32_t o) { return o ^ ((o >> 4) & 0x70); }  // 256B rows

__device__ __forceinline__ uint32_t pk(float a, float b) {
    __nv_bfloat162 h = __floats2bfloat162_rn(a, b);   // .x=a in low 16 bits
    return *reinterpret_cast<uint32_t*>(&h);
}
// split two fp32 into bf16 hi-pair (truncation, exact) and lo-pair (residual)
__device__ __forceinline__ void split2(float f0, float f1, uint32_t& hi, uint32_t& lo) {
    const uint32_t u0 = __float_as_uint(f0), u1 = __float_as_uint(f1);
    asm("prmt.b32 %0, %1, %2, 0x7632;" : "=r"(hi) : "r"(u0), "r"(u1));
    const float h0 = __uint_as_float(u0 & 0xFFFF0000u);
    const float h1 = __uint_as_float(u1 & 0xFFFF0000u);
    lo = pk(f0 - h0, f1 - h1);
}
__device__ __forceinline__ uint32_t pack_hl(float f) {
    __nv_bfloat16 hb = __float2bfloat16(f);
    float hf = __bfloat162float(hb);
    __nv_bfloat16 lb = __float2bfloat16(f - hf);
    return ((uint32_t)__bfloat16_as_ushort(hb) << 16) | (uint32_t)__bfloat16_as_ushort(lb);
}

__device__ __forceinline__ void ldsm4(uint32_t* r, uint32_t addr) {
    asm volatile("ldmatrix.sync.aligned.m8n8.x4.shared.b16 {%0,%1,%2,%3}, [%4];"
                 : "=r"(r[0]), "=r"(r[1]), "=r"(r[2]), "=r"(r[3]) : "r"(addr));
}
__device__ __forceinline__ void ldsm4t(uint32_t* r, uint32_t addr) {
    asm volatile("ldmatrix.sync.aligned.m8n8.x4.trans.shared.b16 {%0,%1,%2,%3}, [%4];"
                 : "=r"(r[0]), "=r"(r[1]), "=r"(r[2]), "=r"(r[3]) : "r"(addr));
}
__device__ __forceinline__ void mma16816(float* c, const uint32_t* a, const uint32_t* b) {
    asm volatile(
        "mma.sync.aligned.m16n8k16.row.col.f32.bf16.bf16.f32 "
        "{%0,%1,%2,%3}, {%4,%5,%6,%7}, {%8,%9}, {%0,%1,%2,%3};"
        : "+f"(c[0]), "+f"(c[1]), "+f"(c[2]), "+f"(c[3])
        : "r"(a[0]), "r"(a[1]), "r"(a[2]), "r"(a[3]), "r"(b[0]), "r"(b[1]));
}

#define MBAR_INIT(addr, cnt) \
    asm volatile("mbarrier.init.shared.b64 [%0], %1;" :: "r"(addr), "r"((uint32_t)(cnt)) : "memory")
#define MBAR_ARRIVE(addr) \
    asm volatile("mbarrier.arrive.shared.b64 _, [%0];" :: "r"(addr) : "memory")
#define MBAR_WAIT(mbar_addr, phase_parity) do {                                            \
    uint32_t _mbar = (uint32_t)(mbar_addr);                                                \
    uint32_t _par  = (uint32_t)(phase_parity);                                             \
    uint32_t _done;                                                                        \
    asm volatile(                                                                          \
        "{\n\t.reg .pred p;\n\t"                                                           \
        "mbarrier.try_wait.parity.acquire.cta.shared::cta.b64 p, [%1], %2;\n\t"            \
        "selp.b32 %0, 1, 0, p;\n\t}"                                                       \
        : "=r"(_done) : "r"(_mbar), "r"(_par) : "memory");                                 \
    if (!_done) {                                                                          \
        asm volatile(                                                                      \
            "{\n\t.reg .pred P1;\n\t"                                                      \
            "WL_%=:\n\t"                                                                   \
            "mbarrier.try_wait.parity.acquire.cta.shared::cta.b64 P1, [%0], %1, 0x989680;\n\t" \
            "@P1 bra.uni WD_%=;\n\t"                                                       \
            "bra.uni WL_%=;\n\t"                                                           \
            "WD_%=:\n\t}"                                                                  \
            :: "r"(_mbar), "r"(_par) : "memory");                                          \
    }                                                                                      \
} while (0)

// ============================================================================
//   KDIM : reduction dim (2048 / 4096),  NTILE: n-tiles per expert (64 / 16)
//   MODE2=false: GEMM1 (A = X fp32 w2048; B = Wgu w8192, paired gate/up cols;
//                       epilogue SwiGLU -> packed g_scr, tile 128x64)
//   MODE2=true : GEMM2 (A = g_scr packed w4096; B = Wd w2048; C fp32 w2048)
// Block: 384 threads = 8 consumer warps (2m x 4n, 64x32 tiles) + 4 producers.
// ============================================================================
template <int KDIM, int NTILE, bool MODE2>
__global__ __launch_bounds__(384, 1) void gemm_ker(const float* __restrict__ A_,
                                                   const float* __restrict__ B_,
                                                   float* __restrict__ C_) {
    extern __shared__ char smem[];
    constexpr int NC  = KDIM / 64;
    constexpr int NWB = MODE2 ? 2048 : 8192;   // B row width

    const int tid  = threadIdx.x;
    const int wid  = tid >> 5;
    const int lane = tid & 31;

    // ---- tile decode: 64-CTA (8m x 8n) supertiles ----
    const int per_e = 8 * NTILE;
    const int e   = blockIdx.x / per_e;
    const int r   = blockIdx.x % per_e;
    const int sup = r >> 6;
    const int r2  = r & 63;
    const int mt  = r2 & 7;
    const int nt  = sup * 8 + (r2 >> 3);

    const uint32_t smbase  = s2u(smem);
    const uint32_t tiles_u = (smbase + 1023) & ~1023u;
    char* tiles = smem + (tiles_u - smbase);
    const uint32_t full0  = smbase;        // full[s]  @ +8s, count=128
    const uint32_t empty0 = smbase + 24;   // empty[s] @ +8s, count=8

    if (tid == 0) {
        #pragma unroll
        for (int s = 0; s < NSTAGE; s++) {
            MBAR_INIT(full0 + 8 * s, 128);
            MBAR_INIT(empty0 + 8 * s, 8);
        }
    }
    __syncthreads();

    if (tid >= 256) {
        // ===================== PRODUCERS (warps 8..11) =====================
        const int pt   = tid - 256;          // 0..127
        const int a_c4 = pt & 15;            // float4/uint4 col in 64-k row
        const int a_r0 = pt >> 4;            // 0..7
        const int b_n4 = pt & 31;            // vec4 col in 128-n row
        const int b_k0 = pt >> 5;            // 0..3

        const float*    Apf = nullptr;
        const uint32_t* Apu = nullptr;
        if (MODE2) Apu = g_scr + (size_t)(e * 1024 + mt * 128) * 4096 + a_c4 * 4;
        else       Apf = A_ + (size_t)(e * 1024 + mt * 128) * 2048 + a_c4 * 4;

        size_t bcol;
        if (MODE2) bcol = (size_t)nt * 128 + b_n4 * 4;
        else       bcol = (b_n4 < 16) ? ((size_t)nt * 64 + b_n4 * 4)
                                      : ((size_t)4096 + nt * 64 + (b_n4 - 16) * 4);
        const float* Bp = B_ + (size_t)e * KDIM * NWB + bcol;

        int s = 0, u = 0;
        for (int c = 0; c < NC; c++) {
            MBAR_WAIT(empty0 + 8 * s, u ^ 1);   // u=0: parity 1 passes immediately
            char* stg = tiles + s * STAGE_BYTES;
            const int kb = c * 64;

            // ---- A tile: 128 rows x 64 k ----
            #pragma unroll
            for (int p = 0; p < 16; p++) {
                const int row = a_r0 + p * 8;
                const uint32_t off = swzA((uint32_t)(row * 128 + a_c4 * 8));
                if (MODE2) {
                    uint4 v = *reinterpret_cast<const uint4*>(Apu + (size_t)row * 4096 + kb);
                    uint32_t h0, h1, l0, l1;
                    asm("prmt.b32 %0, %1, %2, 0x7632;" : "=r"(h0) : "r"(v.x), "r"(v.y));
                    asm("prmt.b32 %0, %1, %2, 0x5410;" : "=r"(l0) : "r"(v.x), "r"(v.y));
                    asm("prmt.b32 %0, %1, %2, 0x7632;" : "=r"(h1) : "r"(v.z), "r"(v.w));
                    asm("prmt.b32 %0, %1, %2, 0x5410;" : "=r"(l1) : "r"(v.z), "r"(v.w));
                    *reinterpret_cast<uint2*>(stg + off)         = make_uint2(h0, h1);
                    *reinterpret_cast<uint2*>(stg + 16384 + off) = make_uint2(l0, l1);
                } else {
                    float4 v = *reinterpret_cast<const float4*>(Apf + (size_t)row * 2048 + kb);
                    uint32_t h0, l0, h1, l1;
                    split2(v.x, v.y, h0, l0);
                    split2(v.z, v.w, h1, l1);
                    *reinterpret_cast<uint2*>(stg + off)         = make_uint2(h0, h1);
                    *reinterpret_cast<uint2*>(stg + 16384 + off) = make_uint2(l0, l1);
                }
            }
            // ---- B tile: 64 k-rows x 128 n ----
            #pragma unroll
            for (int p = 0; p < 16; p++) {
                const int k = b_k0 + p * 4;
                float4 v = *reinterpret_cast<const float4*>(Bp + (size_t)(kb + k) * NWB);
                uint32_t h0, l0, h1, l1;
                split2(v.x, v.y, h0, l0);
                split2(v.z, v.w, h1, l1);
                const uint32_t off = swzB((uint32_t)(k * 256 + b_n4 * 8));
                *reinterpret_cast<uint2*>(stg + 32768 + off) = make_uint2(h0, h1);
                *reinterpret_cast<uint2*>(stg + 49152 + off) = make_uint2(l0, l1);
            }
            MBAR_ARRIVE(full0 + 8 * s);
            if (++s == NSTAGE) { s = 0; u ^= 1; }
        }
        return;
    }

    // ======================= CONSUMERS (warps 0..7) =======================
    // 2(m) x 4(n) warp grid, 64x32 tiles: wm = wid>>2 (0..1), wn = wid&3.
    const int wm = wid >> 2;
    const int wn = wid & 3;

    const int lane15 = lane & 15;
    const int seg    = (lane >> 4) * 16;
    const uint32_t lxor = (uint32_t)((lane & 7) << 4);
    uint32_t a_row[4], b_colx[2];
    #pragma unroll
    for (int st = 0; st < 4; st++)
        a_row[st] = (uint32_t)((wm * 64 + st * 16 + lane15) * 128);
    #pragma unroll
    for (int ng = 0; ng < 2; ng++)
        b_colx[ng] = (uint32_t)(((wn * 32 + ng * 16) * 2 + seg)) ^ lxor;
    const uint32_t b_rowb = (uint32_t)(lane15 * 256);

    float acc[4][4][4];
    #pragma unroll
    for (int st = 0; st < 4; st++)
        #pragma unroll
        for (int j = 0; j < 4; j++)
            #pragma unroll
            for (int i = 0; i < 4; i++) acc[st][j][i] = 0.0f;

    int s = 0, u = 0;
    for (int c = 0; c < NC; c++) {
        MBAR_WAIT(full0 + 8 * s, u);
        const uint32_t AhU = tiles_u + s * STAGE_BYTES;
        const uint32_t AlU = AhU + 16384;
        const uint32_t BhU = AhU + 32768;
        const uint32_t BlU = AhU + 49152;

        #pragma unroll
        for (int ks = 0; ks < 4; ks++) {
            const uint32_t acol = (uint32_t)(ks * 32 + seg) ^ lxor;
            const uint32_t brow = b_rowb + (uint32_t)(ks * 4096);
            uint32_t bh[2][4], bl[2][4];
            #pragma unroll
            for (int ng = 0; ng < 2; ng++) {
                ldsm4t(bh[ng], BhU + brow + b_colx[ng]);
                ldsm4t(bl[ng], BlU + brow + b_colx[ng]);
            }
            #pragma unroll
            for (int st = 0; st < 4; st++) {
                uint32_t ah[4], al[4];
                ldsm4(ah, AhU + a_row[st] + acol);
                ldsm4(al, AlU + a_row[st] + acol);
                #pragma unroll
                for (int ng = 0; ng < 2; ng++)
                    #pragma unroll
                    for (int hf = 0; hf < 2; hf++) {
                        const int j = ng * 2 + hf;
                        mma16816(acc[st][j], ah, &bh[ng][2 * hf]);
                        mma16816(acc[st][j], ah, &bl[ng][2 * hf]);
                        mma16816(acc[st][j], al, &bh[ng][2 * hf]);
                    }
            }
        }
        if (lane == 0) MBAR_ARRIVE(empty0 + 8 * s);
        if (++s == NSTAGE) { s = 0; u ^= 1; }
    }

    // --------------------------- epilogue ---------------------------
    if (MODE2) {
        float* Ce = C_ + (size_t)(e * 1024 + mt * 128) * 2048 + nt * 128;
        #pragma unroll
        for (int st = 0; st < 4; st++)
            #pragma unroll
            for (int j = 0; j < 4; j++) {
                const int r0 = wm * 64 + st * 16 + (lane >> 2);
                const int cc = wn * 32 + j * 8 + (lane & 3) * 2;
                float2 v0; v0.x = acc[st][j][0]; v0.y = acc[st][j][1];
                float2 v1; v1.x = acc[st][j][2]; v1.y = acc[st][j][3];
                *reinterpret_cast<float2*>(Ce + (size_t)r0 * 2048 + cc) = v0;
                *reinterpret_cast<float2*>(Ce + (size_t)(r0 + 8) * 2048 + cc) = v1;
            }
    } else {
        // SwiGLU: cols 0-63 = gate, 64-127 = up. Exchange gate via smem,
        // write inter = up * silu(gate) as packed (hi,lo) u32 to g_scr.
        constexpr int SGP = 68;
        float* sg = reinterpret_cast<float*>(tiles);
        asm volatile("bar.sync 1, 256;" ::: "memory");
        if (wn < 2) {
            #pragma unroll
            for (int st = 0; st < 4; st++)
                #pragma unroll
                for (int j = 0; j < 4; j++) {
                    const int r0 = wm * 64 + st * 16 + (lane >> 2);
                    const int cc = wn * 32 + j * 8 + (lane & 3) * 2;
                    float2 v0; v0.x = acc[st][j][0]; v0.y = acc[st][j][1];
                    float2 v1; v1.x = acc[st][j][2]; v1.y = acc[st][j][3];
                    *reinterpret_cast<float2*>(sg + (size_t)r0 * SGP + cc) = v0;
                    *reinterpret_cast<float2*>(sg + (size_t)(r0 + 8) * SGP + cc) = v1;
                }
        }
        asm volatile("bar.sync 1, 256;" ::: "memory");
        if (wn >= 2) {
            uint32_t* scrb = g_scr + (size_t)(e * 1024 + mt * 128) * 4096 + nt * 64;
            #pragma unroll
            for (int st = 0; st < 4; st++)
                #pragma unroll
                for (int j = 0; j < 4; j++) {
                    const int r0   = wm * 64 + st * 16 + (lane >> 2);
                    const int gcol = (wn - 2) * 32 + j * 8 + (lane & 3) * 2;
                    float2 g0 = *reinterpret_cast<float2*>(sg + (size_t)r0 * SGP + gcol);
                    float2 g1 = *reinterpret_cast<float2*>(sg + (size_t)(r0 + 8) * SGP + gcol);
                    float i0 = acc[st][j][0] * __fdividef(g0.x, 1.0f + __expf(-g0.x));
                    float i1 = acc[st][j][1] * __fdividef(g0.y, 1.0f + __expf(-g0.y));
                    float i2 = acc[st][j][2] * __fdividef(g1.x, 1.0f + __expf(-g1.x));
                    float i3 = acc[st][j][3] * __fdividef(g1.y, 1.0f + __expf(-g1.y));
                    *reinterpret_cast<uint2*>(scrb + (size_t)r0 * 4096 + gcol) =
                        make_uint2(pack_hl(i0), pack_hl(i1));
                    *reinterpret_cast<uint2*>(scrb + (size_t)(r0 + 8) * 4096 + gcol) =
                        make_uint2(pack_hl(i2), pack_hl(i3));
                }
        }
    }
}

// ============================================================================
extern "C" void kernel_launch(void* const* d_in, const int* in_sizes, int n_in,
                              void* d_out, int out_size) {
    const float* X   = (const float*)d_in[0];   // (8192, 2048)
    const float* Wgu = (const float*)d_in[1];   // (8, 2048, 8192)
    const float* Wd  = (const float*)d_in[2];   // (8, 4096, 2048)
    float* out = (float*)d_out;                 // (8192, 2048)

    cudaFuncSetAttribute(gemm_ker<2048, 64, false>,
                         cudaFuncAttributeMaxDynamicSharedMemorySize, SMEM_BYTES);
    cudaFuncSetAttribute(gemm_ker<4096, 16, true>,
                         cudaFuncAttributeMaxDynamicSharedMemorySize, SMEM_BYTES);

    // GEMM1 + SwiGLU: 8 experts * 8 mtiles * 64 gate/up-paired ntiles
    gemm_ker<2048, 64, false><<<4096, 384, SMEM_BYTES>>>(X, Wgu, nullptr);
    // GEMM2: 8 * 8 * 16
    gemm_ker<4096, 16, true><<<1024, 384, SMEM_BYTES>>>(nullptr, Wd, out);
}

// round 7
// speedup vs baseline: 1.8708x; 1.0282x over previous
#include <cuda_runtime.h>
#include <cuda_bf16.h>
#include <stdint.h>

// ============================================================================
// Llama4TextExperts grouped GEMM + SwiGLU, fp32 in/out.
// mma.sync.m16n8k16 bf16 (sm_103-safe), bf16x3 split (ah*bh + ah*bl + al*bh).
// Persistent warp-specialized kernel: 8 consumer warps @64x32 + 4 producer
// warps, 3-stage smem ring that flows continuously across tiles.
//   GEMM1: X(8,1024,2048) @ Wgu(8,2048,8192) -> SwiGLU -> g_scr packed(hi,lo)
//          (gate/up column-paired per warp -> register-local SwiGLU epilogue)
//   GEMM2: g_scr(8,1024,4096) @ Wd(8,4096,2048) -> out(8192,2048) fp32
// ============================================================================

#define STAGE_BYTES 65536
#define NSTAGE 3
#define SMEM_BYTES (1024 + NSTAGE * STAGE_BYTES)
#define NSM 148

// packed intermediate: u32 = (bf16 hi << 16) | bf16 lo
static __device__ uint32_t g_scr[(size_t)8 * 1024 * 4096];   // 128 MB

// ---------------- helpers ----------------
__device__ __forceinline__ uint32_t s2u(const void* p) {
    uint32_t a;
    asm("{ .reg .u64 t; cvta.to.shared.u64 t, %1; cvt.u32.u64 %0, t; }" : "=r"(a) : "l"(p));
    return a;
}
__device__ __forceinline__ uint32_t swzA(uint32_t o) { return o ^ ((o >> 3) & 0x70); }  // 128B rows
__device__ __forceinline__ uint32_t swzB(uint32_t o) { return o ^ ((o >> 4) & 0x70); }  // 256B rows

__device__ __forceinline__ uint32_t pk(float a, float b) {
    __nv_bfloat162 h = __floats2bfloat162_rn(a, b);   // .x=a in low 16 bits
    return *reinterpret_cast<uint32_t*>(&h);
}
// split two fp32 into bf16 hi-pair (truncation, exact) and lo-pair (residual)
__device__ __forceinline__ void split2(float f0, float f1, uint32_t& hi, uint32_t& lo) {
    const uint32_t u0 = __float_as_uint(f0), u1 = __float_as_uint(f1);
    asm("prmt.b32 %0, %1, %2, 0x7632;" : "=r"(hi) : "r"(u0), "r"(u1));
    const float h0 = __uint_as_float(u0 & 0xFFFF0000u);
    const float h1 = __uint_as_float(u1 & 0xFFFF0000u);
    lo = pk(f0 - h0, f1 - h1);
}
__device__ __forceinline__ uint32_t pack_hl(float f) {
    __nv_bfloat16 hb = __float2bfloat16(f);
    float hf = __bfloat162float(hb);
    __nv_bfloat16 lb = __float2bfloat16(f - hf);
    return ((uint32_t)__bfloat16_as_ushort(hb) << 16) | (uint32_t)__bfloat16_as_ushort(lb);
}
__device__ __forceinline__ float silu_mul(float g, float u) {
    return u * __fdividef(g, 1.0f + __expf(-g));
}

__device__ __forceinline__ void ldsm4(uint32_t* r, uint32_t addr) {
    asm volatile("ldmatrix.sync.aligned.m8n8.x4.shared.b16 {%0,%1,%2,%3}, [%4];"
                 : "=r"(r[0]), "=r"(r[1]), "=r"(r[2]), "=r"(r[3]) : "r"(addr));
}
__device__ __forceinline__ void ldsm4t(uint32_t* r, uint32_t addr) {
    asm volatile("ldmatrix.sync.aligned.m8n8.x4.trans.shared.b16 {%0,%1,%2,%3}, [%4];"
                 : "=r"(r[0]), "=r"(r[1]), "=r"(r[2]), "=r"(r[3]) : "r"(addr));
}
__device__ __forceinline__ void mma16816(float* c, const uint32_t* a, const uint32_t* b) {
    asm volatile(
        "mma.sync.aligned.m16n8k16.row.col.f32.bf16.bf16.f32 "
        "{%0,%1,%2,%3}, {%4,%5,%6,%7}, {%8,%9}, {%0,%1,%2,%3};"
        : "+f"(c[0]), "+f"(c[1]), "+f"(c[2]), "+f"(c[3])
        : "r"(a[0]), "r"(a[1]), "r"(a[2]), "r"(a[3]), "r"(b[0]), "r"(b[1]));
}

#define MBAR_INIT(addr, cnt) \
    asm volatile("mbarrier.init.shared.b64 [%0], %1;" :: "r"(addr), "r"((uint32_t)(cnt)) : "memory")
#define MBAR_ARRIVE(addr) \
    asm volatile("mbarrier.arrive.shared.b64 _, [%0];" :: "r"(addr) : "memory")
#define MBAR_WAIT(mbar_addr, phase_parity) do {                                            \
    uint32_t _mbar = (uint32_t)(mbar_addr);                                                \
    uint32_t _par  = (uint32_t)(phase_parity);                                             \
    uint32_t _done;                                                                        \
    asm volatile(                                                                          \
        "{\n\t.reg .pred p;\n\t"                                                           \
        "mbarrier.try_wait.parity.acquire.cta.shared::cta.b64 p, [%1], %2;\n\t"            \
        "selp.b32 %0, 1, 0, p;\n\t}"                                                       \
        : "=r"(_done) : "r"(_mbar), "r"(_par) : "memory");                                 \
    if (!_done) {                                                                          \
        asm volatile(                                                                      \
            "{\n\t.reg .pred P1;\n\t"                                                      \
            "WL_%=:\n\t"                                                                   \
            "mbarrier.try_wait.parity.acquire.cta.shared::cta.b64 P1, [%0], %1, 0x989680;\n\t" \
            "@P1 bra.uni WD_%=;\n\t"                                                       \
            "bra.uni WL_%=;\n\t"                                                           \
            "WD_%=:\n\t}"                                                                  \
            :: "r"(_mbar), "r"(_par) : "memory");                                          \
    }                                                                                      \
} while (0)

// ============================================================================
//   KDIM : reduction dim (2048 / 4096),  NTILE: n-tiles per expert (64 / 16)
//   MODE2=false: GEMM1. A = X fp32 (w2048). B = Wgu (w8192) with warp-paired
//                gate/up columns: tile col n' -> g=n'>>5, pair=n'&15,
//                kind=(n'>>4)&1; global col = nt*64 + g*16 + pair + kind*4096.
//                Epilogue: register-local SwiGLU -> g_scr packed (hi,lo).
//   MODE2=true : GEMM2. A = g_scr packed (w4096); B = Wd (w2048); C fp32.
// Persistent: grid=NSM, each CTA strides the tile list; ring flows across
// tiles (s,u counters never reset). Block: 384 = 8 consumers + 4 producers.
// ============================================================================
template <int KDIM, int NTILE, bool MODE2>
__global__ __launch_bounds__(384, 1) void gemm_ker(const float* __restrict__ A_,
                                                   const float* __restrict__ B_,
                                                   float* __restrict__ C_) {
    extern __shared__ char smem[];
    constexpr int NC   = KDIM / 64;
    constexpr int NWB  = MODE2 ? 2048 : 8192;   // B row width
    constexpr int PERE = 8 * NTILE;             // tiles per expert
    constexpr int TOT  = 8 * PERE;              // total tiles

    const int tid  = threadIdx.x;
    const int wid  = tid >> 5;
    const int lane = tid & 31;

    const uint32_t smbase  = s2u(smem);
    const uint32_t tiles_u = (smbase + 1023) & ~1023u;
    char* tiles = smem + (tiles_u - smbase);
    const uint32_t full0  = smbase;        // full[s]  @ +8s, count=128
    const uint32_t empty0 = smbase + 24;   // empty[s] @ +8s, count=8

    if (tid == 0) {
        #pragma unroll
        for (int s = 0; s < NSTAGE; s++) {
            MBAR_INIT(full0 + 8 * s, 128);
            MBAR_INIT(empty0 + 8 * s, 8);
        }
    }
    __syncthreads();

    if (tid >= 256) {
        // ===================== PRODUCERS (warps 8..11) =====================
        const int pt   = tid - 256;          // 0..127
        const int a_c4 = pt & 15;            // float4/uint4 col in 64-k row
        const int a_r0 = pt >> 4;            // 0..7
        const int b_n4 = pt & 31;            // vec4 col in 128-n row
        const int b_k0 = pt >> 5;            // 0..3

        int s = 0, u = 0;
        for (int t = blockIdx.x; t < TOT; t += gridDim.x) {
            const int e   = t / PERE;
            const int r   = t % PERE;
            const int sup = r >> 6;
            const int r2  = r & 63;
            const int mt  = r2 & 7;
            const int nt  = sup * 8 + (r2 >> 3);

            const float*    Apf = nullptr;
            const uint32_t* Apu = nullptr;
            if (MODE2) Apu = g_scr + (size_t)(e * 1024 + mt * 128) * 4096 + a_c4 * 4;
            else       Apf = A_ + (size_t)(e * 1024 + mt * 128) * 2048 + a_c4 * 4;

            size_t bcol;
            if (MODE2) {
                bcol = (size_t)nt * 128 + b_n4 * 4;
            } else {
                const int np   = b_n4 * 4;
                const int g    = np >> 5;
                const int pair = np & 15;
                const int kind = (np >> 4) & 1;
                bcol = (size_t)nt * 64 + g * 16 + pair + (size_t)kind * 4096;
            }
            const float* Bp = B_ + (size_t)e * KDIM * NWB + bcol;

            for (int c = 0; c < NC; c++) {
                MBAR_WAIT(empty0 + 8 * s, u ^ 1);
                char* stg = tiles + s * STAGE_BYTES;
                const int kb = c * 64;

                // ---- A tile: 128 rows x 64 k ----
                #pragma unroll
                for (int p = 0; p < 16; p++) {
                    const int row = a_r0 + p * 8;
                    const uint32_t off = swzA((uint32_t)(row * 128 + a_c4 * 8));
                    if (MODE2) {
                        uint4 v = *reinterpret_cast<const uint4*>(Apu + (size_t)row * 4096 + kb);
                        uint32_t h0, h1, l0, l1;
                        asm("prmt.b32 %0, %1, %2, 0x7632;" : "=r"(h0) : "r"(v.x), "r"(v.y));
                        asm("prmt.b32 %0, %1, %2, 0x5410;" : "=r"(l0) : "r"(v.x), "r"(v.y));
                        asm("prmt.b32 %0, %1, %2, 0x7632;" : "=r"(h1) : "r"(v.z), "r"(v.w));
                        asm("prmt.b32 %0, %1, %2, 0x5410;" : "=r"(l1) : "r"(v.z), "r"(v.w));
                        *reinterpret_cast<uint2*>(stg + off)         = make_uint2(h0, h1);
                        *reinterpret_cast<uint2*>(stg + 16384 + off) = make_uint2(l0, l1);
                    } else {
                        float4 v = *reinterpret_cast<const float4*>(Apf + (size_t)row * 2048 + kb);
                        uint32_t h0, l0, h1, l1;
                        split2(v.x, v.y, h0, l0);
                        split2(v.z, v.w, h1, l1);
                        *reinterpret_cast<uint2*>(stg + off)         = make_uint2(h0, h1);
                        *reinterpret_cast<uint2*>(stg + 16384 + off) = make_uint2(l0, l1);
                    }
                }
                // ---- B tile: 64 k-rows x 128 n ----
                #pragma unroll
                for (int p = 0; p < 16; p++) {
                    const int k = b_k0 + p * 4;
                    float4 v = *reinterpret_cast<const float4*>(Bp + (size_t)(kb + k) * NWB);
                    uint32_t h0, l0, h1, l1;
                    split2(v.x, v.y, h0, l0);
                    split2(v.z, v.w, h1, l1);
                    const uint32_t off = swzB((uint32_t)(k * 256 + b_n4 * 8));
                    *reinterpret_cast<uint2*>(stg + 32768 + off) = make_uint2(h0, h1);
                    *reinterpret_cast<uint2*>(stg + 49152 + off) = make_uint2(l0, l1);
                }
                MBAR_ARRIVE(full0 + 8 * s);
                if (++s == NSTAGE) { s = 0; u ^= 1; }
            }
        }
        return;
    }

    // ======================= CONSUMERS (warps 0..7) =======================
    // 2(m) x 4(n) warp grid, 64x32 tiles: wm = wid>>2 (0..1), wn = wid&3.
    const int wm = wid >> 2;
    const int wn = wid & 3;

    const int lane15 = lane & 15;
    const int seg    = (lane >> 4) * 16;
    const uint32_t lxor = (uint32_t)((lane & 7) << 4);
    uint32_t a_row[4], b_colx[2];
    #pragma unroll
    for (int st = 0; st < 4; st++)
        a_row[st] = (uint32_t)((wm * 64 + st * 16 + lane15) * 128);
    #pragma unroll
    for (int ng = 0; ng < 2; ng++)
        b_colx[ng] = (uint32_t)(((wn * 32 + ng * 16) * 2 + seg)) ^ lxor;
    const uint32_t b_rowb = (uint32_t)(lane15 * 256);

    int s = 0, u = 0;
    for (int t = blockIdx.x; t < TOT; t += gridDim.x) {
        const int e   = t / PERE;
        const int r   = t % PERE;
        const int sup = r >> 6;
        const int r2  = r & 63;
        const int mt  = r2 & 7;
        const int nt  = sup * 8 + (r2 >> 3);

        float acc[4][4][4];
        #pragma unroll
        for (int st = 0; st < 4; st++)
            #pragma unroll
            for (int j = 0; j < 4; j++)
                #pragma unroll
                for (int i = 0; i < 4; i++) acc[st][j][i] = 0.0f;

        for (int c = 0; c < NC; c++) {
            MBAR_WAIT(full0 + 8 * s, u);
            const uint32_t AhU = tiles_u + s * STAGE_BYTES;
            const uint32_t AlU = AhU + 16384;
            const uint32_t BhU = AhU + 32768;
            const uint32_t BlU = AhU + 49152;

            #pragma unroll
            for (int ks = 0; ks < 4; ks++) {
                const uint32_t acol = (uint32_t)(ks * 32 + seg) ^ lxor;
                const uint32_t brow = b_rowb + (uint32_t)(ks * 4096);
                uint32_t bh[2][4], bl[2][4];
                #pragma unroll
                for (int ng = 0; ng < 2; ng++) {
                    ldsm4t(bh[ng], BhU + brow + b_colx[ng]);
                    ldsm4t(bl[ng], BlU + brow + b_colx[ng]);
                }
                #pragma unroll
                for (int st = 0; st < 4; st++) {
                    uint32_t ah[4], al[4];
                    ldsm4(ah, AhU + a_row[st] + acol);
                    ldsm4(al, AlU + a_row[st] + acol);
                    #pragma unroll
                    for (int ng = 0; ng < 2; ng++)
                        #pragma unroll
                        for (int hf = 0; hf < 2; hf++) {
                            const int j = ng * 2 + hf;
                            mma16816(acc[st][j], ah, &bh[ng][2 * hf]);
                            mma16816(acc[st][j], ah, &bl[ng][2 * hf]);
                            mma16816(acc[st][j], al, &bh[ng][2 * hf]);
                        }
                }
            }
            if (lane == 0) MBAR_ARRIVE(empty0 + 8 * s);
            if (++s == NSTAGE) { s = 0; u ^= 1; }
        }

        // ----------------- epilogue (register-only, overlaps ring) --------
        if (MODE2) {
            float* Ce = C_ + (size_t)(e * 1024 + mt * 128) * 2048 + nt * 128;
            #pragma unroll
            for (int st = 0; st < 4; st++)
                #pragma unroll
                for (int j = 0; j < 4; j++) {
                    const int r0 = wm * 64 + st * 16 + (lane >> 2);
                    const int cc = wn * 32 + j * 8 + (lane & 3) * 2;
                    float2 v0; v0.x = acc[st][j][0]; v0.y = acc[st][j][1];
                    float2 v1; v1.x = acc[st][j][2]; v1.y = acc[st][j][3];
                    *reinterpret_cast<float2*>(Ce + (size_t)r0 * 2048 + cc) = v0;
                    *reinterpret_cast<float2*>(Ce + (size_t)(r0 + 8) * 2048 + cc) = v1;
                }
        } else {
            // gate = acc[st][j] (cols 0..15), up = acc[st][j+2] (cols 16..31),
            // both for output pair p = j*8 + (lane&3)*2. Register-local SwiGLU.
            uint32_t* scrb = g_scr + (size_t)(e * 1024 + mt * 128) * 4096
                           + (size_t)nt * 64 + wn * 16;
            #pragma unroll
            for (int st = 0; st < 4; st++)
                #pragma unroll
                for (int j = 0; j < 2; j++) {
                    const int r0 = wm * 64 + st * 16 + (lane >> 2);
                    const int cc = j * 8 + (lane & 3) * 2;
                    const float i0 = silu_mul(acc[st][j][0], acc[st][j + 2][0]);
                    const float i1 = silu_mul(acc[st][j][1], acc[st][j + 2][1]);
                    const float i2 = silu_mul(acc[st][j][2], acc[st][j + 2][2]);
                    const float i3 = silu_mul(acc[st][j][3], acc[st][j + 2][3]);
                    *reinterpret_cast<uint2*>(scrb + (size_t)r0 * 4096 + cc) =
                        make_uint2(pack_hl(i0), pack_hl(i1));
                    *reinterpret_cast<uint2*>(scrb + (size_t)(r0 + 8) * 4096 + cc) =
                        make_uint2(pack_hl(i2), pack_hl(i3));
                }
        }
    }
}

// ============================================================================
extern "C" void kernel_launch(void* const* d_in, const int* in_sizes, int n_in,
                              void* d_out, int out_size) {
    const float* X   = (const float*)d_in[0];   // (8192, 2048)
    const float* Wgu = (const float*)d_in[1];   // (8, 2048, 8192)
    const float* Wd  = (const float*)d_in[2];   // (8, 4096, 2048)
    float* out = (float*)d_out;                 // (8192, 2048)

    cudaFuncSetAttribute(gemm_ker<2048, 64, false>,
                         cudaFuncAttributeMaxDynamicSharedMemorySize, SMEM_BYTES);
    cudaFuncSetAttribute(gemm_ker<4096, 16, true>,
                         cudaFuncAttributeMaxDynamicSharedMemorySize, SMEM_BYTES);

    // Persistent: one CTA per SM, tiles strided inside the kernel.
    gemm_ker<2048, 64, false><<<NSM, 384, SMEM_BYTES>>>(X, Wgu, nullptr);
    gemm_ker<4096, 16, true><<<NSM, 384, SMEM_BYTES>>>(nullptr, Wd, out);
}

// round 8
// speedup vs baseline: 1.8726x; 1.0010x over previous
#include <cuda_runtime.h>
#include <cuda_bf16.h>
#include <stdint.h>

// ============================================================================
// Llama4TextExperts grouped GEMM + SwiGLU, fp32 in/out.
// mma.sync.m16n8k16 bf16 (sm_103-safe), bf16x3 split (ah*bh + ah*bl + al*bh).
// Persistent warp-specialized kernel: 8 consumer warps @64x32 + 4 producer
// warps, 3-stage smem ring that flows continuously across tiles.
//   GEMM1: X(8,1024,2048) @ Wgu(8,2048,8192) -> SwiGLU -> g_scr packed(hi,lo)
//          (gate/up column-paired per warp -> register-local SwiGLU epilogue)
//   GEMM2: g_scr(8,1024,4096) @ Wd(8,4096,2048) -> out(8192,2048) fp32
// ============================================================================

#define STAGE_BYTES 65536
#define NSTAGE 3
#define SMEM_BYTES (1024 + NSTAGE * STAGE_BYTES)
#define NSM 148

// packed intermediate: u32 = (bf16 hi << 16) | bf16 lo
static __device__ uint32_t g_scr[(size_t)8 * 1024 * 4096];   // 128 MB

// ---------------- helpers ----------------
__device__ __forceinline__ uint32_t s2u(const void* p) {
    uint32_t a;
    asm("{ .reg .u64 t; cvta.to.shared.u64 t, %1; cvt.u32.u64 %0, t; }" : "=r"(a) : "l"(p));
    return a;
}
__device__ __forceinline__ uint32_t swzA(uint32_t o) { return o ^ ((o >> 3) & 0x70); }  // 128B rows
__device__ __forceinline__ uint32_t swzB(uint32_t o) { return o ^ ((o >> 4) & 0x70); }  // 256B rows

__device__ __forceinline__ uint32_t pk(float a, float b) {
    __nv_bfloat162 h = __floats2bfloat162_rn(a, b);   // .x=a in low 16 bits
    return *reinterpret_cast<uint32_t*>(&h);
}
// split two fp32 into bf16 hi-pair (truncation, exact) and lo-pair (residual)
__device__ __forceinline__ void split2(float f0, float f1, uint32_t& hi, uint32_t& lo) {
    const uint32_t u0 = __float_as_uint(f0), u1 = __float_as_uint(f1);
    asm("prmt.b32 %0, %1, %2, 0x7632;" : "=r"(hi) : "r"(u0), "r"(u1));
    const float h0 = __uint_as_float(u0 & 0xFFFF0000u);
    const float h1 = __uint_as_float(u1 & 0xFFFF0000u);
    lo = pk(f0 - h0, f1 - h1);
}
__device__ __forceinline__ uint32_t pack_hl(float f) {
    __nv_bfloat16 hb = __float2bfloat16(f);
    float hf = __bfloat162float(hb);
    __nv_bfloat16 lb = __float2bfloat16(f - hf);
    return ((uint32_t)__bfloat16_as_ushort(hb) << 16) | (uint32_t)__bfloat16_as_ushort(lb);
}
__device__ __forceinline__ float silu_mul(float g, float u) {
    return u * __fdividef(g, 1.0f + __expf(-g));
}

__device__ __forceinline__ void ldsm4(uint32_t* r, uint32_t addr) {
    asm volatile("ldmatrix.sync.aligned.m8n8.x4.shared.b16 {%0,%1,%2,%3}, [%4];"
                 : "=r"(r[0]), "=r"(r[1]), "=r"(r[2]), "=r"(r[3]) : "r"(addr));
}
__device__ __forceinline__ void ldsm4t(uint32_t* r, uint32_t addr) {
    asm volatile("ldmatrix.sync.aligned.m8n8.x4.trans.shared.b16 {%0,%1,%2,%3}, [%4];"
                 : "=r"(r[0]), "=r"(r[1]), "=r"(r[2]), "=r"(r[3]) : "r"(addr));
}
__device__ __forceinline__ void mma16816(float* c, const uint32_t* a, const uint32_t* b) {
    asm volatile(
        "mma.sync.aligned.m16n8k16.row.col.f32.bf16.bf16.f32 "
        "{%0,%1,%2,%3}, {%4,%5,%6,%7}, {%8,%9}, {%0,%1,%2,%3};"
        : "+f"(c[0]), "+f"(c[1]), "+f"(c[2]), "+f"(c[3])
        : "r"(a[0]), "r"(a[1]), "r"(a[2]), "r"(a[3]), "r"(b[0]), "r"(b[1]));
}

#define MBAR_INIT(addr, cnt) \
    asm volatile("mbarrier.init.shared.b64 [%0], %1;" :: "r"(addr), "r"((uint32_t)(cnt)) : "memory")
#define MBAR_ARRIVE(addr) \
    asm volatile("mbarrier.arrive.shared.b64 _, [%0];" :: "r"(addr) : "memory")
#define MBAR_WAIT(mbar_addr, phase_parity) do {                                            \
    uint32_t _mbar = (uint32_t)(mbar_addr);                                                \
    uint32_t _par  = (uint32_t)(phase_parity);                                             \
    uint32_t _done;                                                                        \
    asm volatile(                                                                          \
        "{\n\t.reg .pred p;\n\t"                                                           \
        "mbarrier.try_wait.parity.acquire.cta.shared::cta.b64 p, [%1], %2;\n\t"            \
        "selp.b32 %0, 1, 0, p;\n\t}"                                                       \
        : "=r"(_done) : "r"(_mbar), "r"(_par) : "memory");                                 \
    if (!_done) {                                                                          \
        asm volatile(                                                                      \
            "{\n\t.reg .pred P1;\n\t"                                                      \
            "WL_%=:\n\t"                                                                   \
            "mbarrier.try_wait.parity.acquire.cta.shared::cta.b64 P1, [%0], %1, 0x989680;\n\t" \
            "@P1 bra.uni WD_%=;\n\t"                                                       \
            "bra.uni WL_%=;\n\t"                                                           \
            "WD_%=:\n\t}"                                                                  \
            :: "r"(_mbar), "r"(_par) : "memory");                                          \
    }                                                                                      \
} while (0)

// ============================================================================
//   KDIM : reduction dim (2048 / 4096),  NTILE: n-tiles per expert (64 / 16)
//   MODE2=false: GEMM1. A = X fp32 (w2048). B = Wgu (w8192) with warp-paired
//                gate/up columns: tile col n' -> g=n'>>5, pair=n'&15,
//                kind=(n'>>4)&1; global col = nt*64 + g*16 + pair + kind*4096.
//                Epilogue: register-local SwiGLU -> g_scr packed (hi,lo).
//   MODE2=true : GEMM2. A = g_scr packed (w4096); B = Wd (w2048); C fp32.
// Persistent: grid=NSM, each CTA strides the tile list; ring flows across
// tiles (s,u counters never reset). Block: 384 = 8 consumers + 4 producers.
// ============================================================================
template <int KDIM, int NTILE, bool MODE2>
__global__ __launch_bounds__(384, 1) void gemm_ker(const float* __restrict__ A_,
                                                   const float* __restrict__ B_,
                                                   float* __restrict__ C_) {
    extern __shared__ char smem[];
    constexpr int NC   = KDIM / 64;
    constexpr int NWB  = MODE2 ? 2048 : 8192;   // B row width
    constexpr int PERE = 8 * NTILE;             // tiles per expert
    constexpr int TOT  = 8 * PERE;              // total tiles

    const int tid  = threadIdx.x;
    const int wid  = tid >> 5;
    const int lane = tid & 31;

    const uint32_t smbase  = s2u(smem);
    const uint32_t tiles_u = (smbase + 1023) & ~1023u;
    char* tiles = smem + (tiles_u - smbase);
    const uint32_t full0  = smbase;        // full[s]  @ +8s, count=128
    const uint32_t empty0 = smbase + 24;   // empty[s] @ +8s, count=8

    if (tid == 0) {
        #pragma unroll
        for (int s = 0; s < NSTAGE; s++) {
            MBAR_INIT(full0 + 8 * s, 128);
            MBAR_INIT(empty0 + 8 * s, 8);
        }
    }
    __syncthreads();

    if (tid >= 256) {
        // ===================== PRODUCERS (warps 8..11) =====================
        const int pt   = tid - 256;          // 0..127
        const int a_c4 = pt & 15;            // float4/uint4 col in 64-k row
        const int a_r0 = pt >> 4;            // 0..7
        const int b_n4 = pt & 31;            // vec4 col in 128-n row
        const int b_k0 = pt >> 5;            // 0..3

        int s = 0, u = 0;
        for (int t = blockIdx.x; t < TOT; t += gridDim.x) {
            const int e   = t / PERE;
            const int r   = t % PERE;
            const int sup = r >> 6;
            const int r2  = r & 63;
            const int mt  = r2 & 7;
            const int nt  = sup * 8 + (r2 >> 3);

            const float*    Apf = nullptr;
            const uint32_t* Apu = nullptr;
            if (MODE2) Apu = g_scr + (size_t)(e * 1024 + mt * 128) * 4096 + a_c4 * 4;
            else       Apf = A_ + (size_t)(e * 1024 + mt * 128) * 2048 + a_c4 * 4;

            size_t bcol;
            if (MODE2) {
                bcol = (size_t)nt * 128 + b_n4 * 4;
            } else {
                const int np   = b_n4 * 4;
                const int g    = np >> 5;
                const int pair = np & 15;
                const int kind = (np >> 4) & 1;
                bcol = (size_t)nt * 64 + g * 16 + pair + (size_t)kind * 4096;
            }
            const float* Bp = B_ + (size_t)e * KDIM * NWB + bcol;

            for (int c = 0; c < NC; c++) {
                MBAR_WAIT(empty0 + 8 * s, u ^ 1);
                char* stg = tiles + s * STAGE_BYTES;
                const int kb = c * 64;

                // ---- A tile: 128 rows x 64 k ----
                #pragma unroll
                for (int p = 0; p < 16; p++) {
                    const int row = a_r0 + p * 8;
                    const uint32_t off = swzA((uint32_t)(row * 128 + a_c4 * 8));
                    if (MODE2) {
                        uint4 v = *reinterpret_cast<const uint4*>(Apu + (size_t)row * 4096 + kb);
                        uint32_t h0, h1, l0, l1;
                        asm("prmt.b32 %0, %1, %2, 0x7632;" : "=r"(h0) : "r"(v.x), "r"(v.y));
                        asm("prmt.b32 %0, %1, %2, 0x5410;" : "=r"(l0) : "r"(v.x), "r"(v.y));
                        asm("prmt.b32 %0, %1, %2, 0x7632;" : "=r"(h1) : "r"(v.z), "r"(v.w));
                        asm("prmt.b32 %0, %1, %2, 0x5410;" : "=r"(l1) : "r"(v.z), "r"(v.w));
                        *reinterpret_cast<uint2*>(stg + off)         = make_uint2(h0, h1);
                        *reinterpret_cast<uint2*>(stg + 16384 + off) = make_uint2(l0, l1);
                    } else {
                        float4 v = *reinterpret_cast<const float4*>(Apf + (size_t)row * 2048 + kb);
                        uint32_t h0, l0, h1, l1;
                        split2(v.x, v.y, h0, l0);
                        split2(v.z, v.w, h1, l1);
                        *reinterpret_cast<uint2*>(stg + off)         = make_uint2(h0, h1);
                        *reinterpret_cast<uint2*>(stg + 16384 + off) = make_uint2(l0, l1);
                    }
                }
                // ---- B tile: 64 k-rows x 128 n ----
                #pragma unroll
                for (int p = 0; p < 16; p++) {
                    const int k = b_k0 + p * 4;
                    float4 v = *reinterpret_cast<const float4*>(Bp + (size_t)(kb + k) * NWB);
                    uint32_t h0, l0, h1, l1;
                    split2(v.x, v.y, h0, l0);
                    split2(v.z, v.w, h1, l1);
                    const uint32_t off = swzB((uint32_t)(k * 256 + b_n4 * 8));
                    *reinterpret_cast<uint2*>(stg + 32768 + off) = make_uint2(h0, h1);
                    *reinterpret_cast<uint2*>(stg + 49152 + off) = make_uint2(l0, l1);
                }
                MBAR_ARRIVE(full0 + 8 * s);
                if (++s == NSTAGE) { s = 0; u ^= 1; }
            }
        }
        return;
    }

    // ======================= CONSUMERS (warps 0..7) =======================
    // 2(m) x 4(n) warp grid, 64x32 tiles: wm = wid>>2 (0..1), wn = wid&3.
    const int wm = wid >> 2;
    const int wn = wid & 3;

    const int lane15 = lane & 15;
    const int seg    = (lane >> 4) * 16;
    const uint32_t lxor = (uint32_t)((lane & 7) << 4);
    uint32_t a_row[4], b_colx[2];
    #pragma unroll
    for (int st = 0; st < 4; st++)
        a_row[st] = (uint32_t)((wm * 64 + st * 16 + lane15) * 128);
    #pragma unroll
    for (int ng = 0; ng < 2; ng++)
        b_colx[ng] = (uint32_t)(((wn * 32 + ng * 16) * 2 + seg)) ^ lxor;
    const uint32_t b_rowb = (uint32_t)(lane15 * 256);

    int s = 0, u = 0;
    for (int t = blockIdx.x; t < TOT; t += gridDim.x) {
        const int e   = t / PERE;
        const int r   = t % PERE;
        const int sup = r >> 6;
        const int r2  = r & 63;
        const int mt  = r2 & 7;
        const int nt  = sup * 8 + (r2 >> 3);

        float acc[4][4][4];
        #pragma unroll
        for (int st = 0; st < 4; st++)
            #pragma unroll
            for (int j = 0; j < 4; j++)
                #pragma unroll
                for (int i = 0; i < 4; i++) acc[st][j][i] = 0.0f;

        for (int c = 0; c < NC; c++) {
            MBAR_WAIT(full0 + 8 * s, u);
            const uint32_t AhU = tiles_u + s * STAGE_BYTES;
            const uint32_t AlU = AhU + 16384;
            const uint32_t BhU = AhU + 32768;
            const uint32_t BlU = AhU + 49152;

            #pragma unroll
            for (int ks = 0; ks < 4; ks++) {
                const uint32_t acol = (uint32_t)(ks * 32 + seg) ^ lxor;
                const uint32_t brow = b_rowb + (uint32_t)(ks * 4096);
                uint32_t bh[2][4], bl[2][4];
                #pragma unroll
                for (int ng = 0; ng < 2; ng++) {
                    ldsm4t(bh[ng], BhU + brow + b_colx[ng]);
                    ldsm4t(bl[ng], BlU + brow + b_colx[ng]);
                }
                #pragma unroll
                for (int st = 0; st < 4; st++) {
                    uint32_t ah[4], al[4];
                    ldsm4(ah, AhU + a_row[st] + acol);
                    ldsm4(al, AlU + a_row[st] + acol);
                    #pragma unroll
                    for (int ng = 0; ng < 2; ng++)
                        #pragma unroll
                        for (int hf = 0; hf < 2; hf++) {
                            const int j = ng * 2 + hf;
                            mma16816(acc[st][j], ah, &bh[ng][2 * hf]);
                            mma16816(acc[st][j], ah, &bl[ng][2 * hf]);
                            mma16816(acc[st][j], al, &bh[ng][2 * hf]);
                        }
                }
            }
            if (lane == 0) MBAR_ARRIVE(empty0 + 8 * s);
            if (++s == NSTAGE) { s = 0; u ^= 1; }
        }

        // ----------------- epilogue (register-only, overlaps ring) --------
        if (MODE2) {
            float* Ce = C_ + (size_t)(e * 1024 + mt * 128) * 2048 + nt * 128;
            #pragma unroll
            for (int st = 0; st < 4; st++)
                #pragma unroll
                for (int j = 0; j < 4; j++) {
                    const int r0 = wm * 64 + st * 16 + (lane >> 2);
                    const int cc = wn * 32 + j * 8 + (lane & 3) * 2;
                    float2 v0; v0.x = acc[st][j][0]; v0.y = acc[st][j][1];
                    float2 v1; v1.x = acc[st][j][2]; v1.y = acc[st][j][3];
                    *reinterpret_cast<float2*>(Ce + (size_t)r0 * 2048 + cc) = v0;
                    *reinterpret_cast<float2*>(Ce + (size_t)(r0 + 8) * 2048 + cc) = v1;
                }
        } else {
            // gate = acc[st][j] (cols 0..15), up = acc[st][j+2] (cols 16..31),
            // both for output pair p = j*8 + (lane&3)*2. Register-local SwiGLU.
            uint32_t* scrb = g_scr + (size_t)(e * 1024 + mt * 128) * 4096
                           + (size_t)nt * 64 + wn * 16;
            #pragma unroll
            for (int st = 0; st < 4; st++)
                #pragma unroll
                for (int j = 0; j < 2; j++) {
                    const int r0 = wm * 64 + st * 16 + (lane >> 2);
                    const int cc = j * 8 + (lane & 3) * 2;
                    const float i0 = silu_mul(acc[st][j][0], acc[st][j + 2][0]);
                    const float i1 = silu_mul(acc[st][j][1], acc[st][j + 2][1]);
                    const float i2 = silu_mul(acc[st][j][2], acc[st][j + 2][2]);
                    const float i3 = silu_mul(acc[st][j][3], acc[st][j + 2][3]);
                    *reinterpret_cast<uint2*>(scrb + (size_t)r0 * 4096 + cc) =
                        make_uint2(pack_hl(i0), pack_hl(i1));
                    *reinterpret_cast<uint2*>(scrb + (size_t)(r0 + 8) * 4096 + cc) =
                        make_uint2(pack_hl(i2), pack_hl(i3));
                }
        }
    }
}

// ============================================================================
extern "C" void kernel_launch(void* const* d_in, const int* in_sizes, int n_in,
                              void* d_out, int out_size) {
    const float* X   = (const float*)d_in[0];   // (8192, 2048)
    const float* Wgu = (const float*)d_in[1];   // (8, 2048, 8192)
    const float* Wd  = (const float*)d_in[2];   // (8, 4096, 2048)
    float* out = (float*)d_out;                 // (8192, 2048)

    cudaFuncSetAttribute(gemm_ker<2048, 64, false>,
                         cudaFuncAttributeMaxDynamicSharedMemorySize, SMEM_BYTES);
    cudaFuncSetAttribute(gemm_ker<4096, 16, true>,
                         cudaFuncAttributeMaxDynamicSharedMemorySize, SMEM_BYTES);

    // Persistent: one CTA per SM, tiles strided inside the kernel.
    gemm_ker<2048, 64, false><<<NSM, 384, SMEM_BYTES>>>(X, Wgu, nullptr);
    gemm_ker<4096, 16, true><<<NSM, 384, SMEM_BYTES>>>(nullptr, Wd, out);
}